// round 1
// baseline (speedup 1.0000x reference)
#include <cuda_runtime.h>
#include <math.h>
#include <stdint.h>

// Problem constants (fixed shapes per reference)
#define NN      100000
#define FF      512
#define HH      64
#define CC      32
#define EE      3300000        // N_EDGES + N_NODES (self loops)
#define ALPHA_F 0.1f
#define NITER   10

// ---------------- device scratch (allocation-free) ----------------
__device__ int   g_cnt[NN];        // histogram, then scatter cursor
__device__ int   g_rowptr[NN + 1];
__device__ int   g_cole[EE];
__device__ float g_vale[EE];
__device__ float g_local[(size_t)NN * CC];
__device__ float g_pA[(size_t)NN * CC];
__device__ float g_pB[(size_t)NN * CC];
__device__ int   g_bsum[64];

// ---------------- CSR build ----------------
__global__ void k_zero_cnt() {
    int i = blockIdx.x * blockDim.x + threadIdx.x;
    if (i < NN) g_cnt[i] = 0;
}

__global__ void k_hist(const int* __restrict__ rows, int E) {
    int e = blockIdx.x * blockDim.x + threadIdx.x;
    if (e < E) atomicAdd(&g_cnt[rows[e]], 1);
}

// scanA: per-block (2048 elems) sums
__global__ void k_scanA() {
    __shared__ int sd[1024];
    int t = threadIdx.x;
    int base = blockIdx.x * 2048;
    int i0 = base + 2 * t;
    int v = 0;
    if (i0 < NN)     v += g_cnt[i0];
    if (i0 + 1 < NN) v += g_cnt[i0 + 1];
    sd[t] = v;
    __syncthreads();
    for (int o = 512; o > 0; o >>= 1) {
        if (t < o) sd[t] += sd[t + o];
        __syncthreads();
    }
    if (t == 0) g_bsum[blockIdx.x] = sd[0];
}

// scanB: exclusive scan of block sums (tiny, 1 thread)
__global__ void k_scanB(int nb) {
    if (threadIdx.x == 0 && blockIdx.x == 0) {
        int acc = 0;
        for (int i = 0; i < nb; i++) { int s = g_bsum[i]; g_bsum[i] = acc; acc += s; }
    }
}

// scanC: per-block exclusive scan + block offset -> rowptr + cursor
__global__ void k_scanC(int E) {
    __shared__ int sd[1024];
    int t = threadIdx.x;
    int base = blockIdx.x * 2048;
    int i0 = base + 2 * t;
    int v0 = (i0 < NN)     ? g_cnt[i0]     : 0;
    int v1 = (i0 + 1 < NN) ? g_cnt[i0 + 1] : 0;
    int tsum = v0 + v1;
    sd[t] = tsum;
    __syncthreads();
    for (int off = 1; off < 1024; off <<= 1) {
        int xval = (t >= off) ? sd[t - off] : 0;
        __syncthreads();
        sd[t] += xval;
        __syncthreads();
    }
    int excl = sd[t] - tsum + g_bsum[blockIdx.x];
    if (i0 < NN)     { g_rowptr[i0]     = excl;      g_cnt[i0]     = excl; }
    if (i0 + 1 < NN) { g_rowptr[i0 + 1] = excl + v0; g_cnt[i0 + 1] = excl + v0; }
    if (blockIdx.x == 0 && t == 0) g_rowptr[NN] = E;
}

__global__ void k_scatter(const int* __restrict__ rows, const int* __restrict__ cols,
                          const float* __restrict__ vals, int E) {
    int e = blockIdx.x * blockDim.x + threadIdx.x;
    if (e >= E) return;
    int r = rows[e];
    int pos = atomicAdd(&g_cnt[r], 1);
    g_cole[pos] = cols[e];
    g_vale[pos] = vals[e];
}

// ---------------- MLP: local = tanh(x @ w1^T) @ w2^T ----------------
// block = 256 threads (8 warps), each warp handles 4 rows at a time.
// Lane j owns output features j and j+32 of h -> no cross-lane reductions.
// SMEM: w1 padded stride-65 (conflict free), w2 transposed, x tiles, h tiles.
#define MLP_SMEM_FLOATS (512*65 + 64*32 + 8*4*512 + 8*4*64)
#define MLP_SMEM_BYTES  (MLP_SMEM_FLOATS * 4)

__global__ void __launch_bounds__(256, 1)
k_mlp(const float* __restrict__ x, const float* __restrict__ w1,
      const float* __restrict__ w2, int ntiles) {
    extern __shared__ float sm[];
    float* w1s = sm;                    // [512][65]
    float* w2t = sm + 512 * 65;         // [64][32]  w2t[j*32+c] = w2[c][j]
    float* xs  = w2t + 64 * 32;         // [32][512]
    float* hs  = xs + 32 * 512;         // [32][64]

    int tid  = threadIdx.x;
    int warp = tid >> 5;
    int lane = tid & 31;

    for (int idx = tid; idx < HH * FF; idx += 256) {
        int j = idx >> 9, k = idx & 511;
        w1s[k * 65 + j] = w1[idx];
    }
    for (int idx = tid; idx < CC * HH; idx += 256) {
        int c = idx >> 6, j = idx & 63;
        w2t[j * 32 + c] = w2[idx];
    }
    __syncthreads();

    for (int tile = blockIdx.x; tile < ntiles; tile += gridDim.x) {
        int rowbase = tile * 32 + warp * 4;

        // load 4 rows of x (coalesced float4)
        #pragma unroll
        for (int r = 0; r < 4; r++) {
            int row = rowbase + r;
            float4* dst = (float4*)(xs + (warp * 4 + r) * 512);
            if (row < NN) {
                const float4* src = (const float4*)(x + (size_t)row * 512);
                #pragma unroll
                for (int i = 0; i < 4; i++) dst[i * 32 + lane] = src[i * 32 + lane];
            } else {
                float4 z = make_float4(0.f, 0.f, 0.f, 0.f);
                #pragma unroll
                for (int i = 0; i < 4; i++) dst[i * 32 + lane] = z;
            }
        }
        __syncwarp();

        float acc[4][2] = {};
        const float* xw = xs + warp * 4 * 512;
        #pragma unroll 4
        for (int k = 0; k < 512; k++) {
            float wlo = w1s[k * 65 + lane];
            float whi = w1s[k * 65 + lane + 32];
            #pragma unroll
            for (int r = 0; r < 4; r++) {
                float xv = xw[r * 512 + k];
                acc[r][0] = fmaf(xv, wlo, acc[r][0]);
                acc[r][1] = fmaf(xv, whi, acc[r][1]);
            }
        }

        #pragma unroll
        for (int r = 0; r < 4; r++) {
            hs[(warp * 4 + r) * 64 + lane]      = tanhf(acc[r][0]);
            hs[(warp * 4 + r) * 64 + lane + 32] = tanhf(acc[r][1]);
        }
        __syncwarp();

        #pragma unroll
        for (int r = 0; r < 4; r++) {
            int row = rowbase + r;
            if (row < NN) {
                const float* hrow = hs + (warp * 4 + r) * 64;
                float a = 0.f;
                #pragma unroll
                for (int j = 0; j < 64; j++)
                    a = fmaf(hrow[j], w2t[j * 32 + lane], a);
                g_local[(size_t)row * 32 + lane] = a;
            }
        }
        __syncwarp();
    }
}

// ---------------- SpMM: pout = A_hat @ pin + ALPHA * local ----------------
// warp per row, lane = feature. Gathers of pin rows are fully coalesced 128B
// and L2-resident (pin = 12.8 MB). 4-deep manual unroll for memory ILP.
__global__ void __launch_bounds__(256)
k_spmm(const float* __restrict__ pin, float* __restrict__ pout) {
    int gw = (blockIdx.x * blockDim.x + threadIdx.x) >> 5;
    if (gw >= NN) return;
    int lane = threadIdx.x & 31;

    int s = g_rowptr[gw];
    int e = g_rowptr[gw + 1];
    float acc = ALPHA_F * g_local[(size_t)gw * 32 + lane];

    for (int base = s; base < e; base += 32) {
        int idx = base + lane;
        int col = 0; float v = 0.f;
        if (idx < e) { col = g_cole[idx]; v = g_vale[idx]; }
        int m = e - base; if (m > 32) m = 32;

        int t = 0;
        for (; t + 4 <= m; t += 4) {
            int   c0 = __shfl_sync(0xffffffffu, col, t);
            int   c1 = __shfl_sync(0xffffffffu, col, t + 1);
            int   c2 = __shfl_sync(0xffffffffu, col, t + 2);
            int   c3 = __shfl_sync(0xffffffffu, col, t + 3);
            float v0 = __shfl_sync(0xffffffffu, v, t);
            float v1 = __shfl_sync(0xffffffffu, v, t + 1);
            float v2 = __shfl_sync(0xffffffffu, v, t + 2);
            float v3 = __shfl_sync(0xffffffffu, v, t + 3);
            float p0 = pin[(size_t)c0 * 32 + lane];
            float p1 = pin[(size_t)c1 * 32 + lane];
            float p2 = pin[(size_t)c2 * 32 + lane];
            float p3 = pin[(size_t)c3 * 32 + lane];
            acc = fmaf(v0, p0, acc);
            acc = fmaf(v1, p1, acc);
            acc = fmaf(v2, p2, acc);
            acc = fmaf(v3, p3, acc);
        }
        for (; t < m; t++) {
            int   cc = __shfl_sync(0xffffffffu, col, t);
            float vv = __shfl_sync(0xffffffffu, v, t);
            acc = fmaf(vv, pin[(size_t)cc * 32 + lane], acc);
        }
    }
    pout[(size_t)gw * 32 + lane] = acc;
}

// ---------------- launch ----------------
extern "C" void kernel_launch(void* const* d_in, const int* in_sizes, int n_in,
                              void* d_out, int out_size) {
    const float* x    = (const float*)d_in[0];
    const float* w1   = (const float*)d_in[1];
    const float* w2   = (const float*)d_in[2];
    const int*   rows = (const int*)d_in[3];
    const int*   cols = (const int*)d_in[4];
    const float* vals = (const float*)d_in[5];
    float*       out  = (float*)d_out;

    int E = in_sizes[3];
    if (E > EE) E = EE;

    // CSR build
    k_zero_cnt<<<(NN + 255) / 256, 256>>>();
    k_hist<<<(E + 255) / 256, 256>>>(rows, E);
    int nb = (NN + 2047) / 2048;  // 49
    k_scanA<<<nb, 1024>>>();
    k_scanB<<<1, 32>>>(nb);
    k_scanC<<<nb, 1024>>>(E);
    k_scatter<<<(E + 255) / 256, 256>>>(rows, cols, vals, E);

    // MLP
    cudaFuncSetAttribute(k_mlp, cudaFuncAttributeMaxDynamicSharedMemorySize, MLP_SMEM_BYTES);
    int ntiles = (NN + 31) / 32;
    k_mlp<<<304, 256, MLP_SMEM_BYTES>>>(x, w1, w2, ntiles);

    // power iterations (ping-pong, last one straight into d_out)
    float *pA, *pB, *plocal;
    cudaGetSymbolAddress((void**)&pA, g_pA);
    cudaGetSymbolAddress((void**)&pB, g_pB);
    cudaGetSymbolAddress((void**)&plocal, g_local);

    const float* pin = plocal;
    int grid = (NN * 32 + 255) / 256;  // warp per row, 8 rows/block
    for (int i = 0; i < NITER; i++) {
        float* po = (i == NITER - 1) ? out : ((i & 1) ? pB : pA);
        k_spmm<<<grid, 256>>>(pin, po);
        pin = po;
    }
}

// round 2
// speedup vs baseline: 1.1946x; 1.1946x over previous
#include <cuda_runtime.h>
#include <cuda_fp16.h>
#include <math.h>
#include <stdint.h>

// Problem constants (fixed shapes per reference)
#define NN      100000
#define FF      512
#define HH      64
#define CC      32
#define EE      3300000        // N_EDGES + N_NODES (self loops)
#define ALPHA_F 0.1f
#define NITER   10

// ---------------- device scratch (allocation-free) ----------------
__device__ int    g_cnt[NN];        // histogram, then scatter cursor
__device__ int    g_rowptr[NN + 1];
__device__ int2   g_edge[EE];       // {col, f32 val bits} interleaved
__device__ __half g_local_h[(size_t)NN * CC];
__device__ __half g_pA[(size_t)NN * CC];
__device__ __half g_pB[(size_t)NN * CC];
__device__ int    g_bsum[64];

// ---------------- CSR build ----------------
__global__ void k_zero_cnt() {
    int i = blockIdx.x * blockDim.x + threadIdx.x;
    if (i < NN) g_cnt[i] = 0;
}

__global__ void k_hist(const int* __restrict__ rows, int E) {
    int e = blockIdx.x * blockDim.x + threadIdx.x;
    if (e < E) atomicAdd(&g_cnt[rows[e]], 1);
}

// scanA: per-block (2048 elems) sums
__global__ void k_scanA() {
    __shared__ int sd[1024];
    int t = threadIdx.x;
    int base = blockIdx.x * 2048;
    int i0 = base + 2 * t;
    int v = 0;
    if (i0 < NN)     v += g_cnt[i0];
    if (i0 + 1 < NN) v += g_cnt[i0 + 1];
    sd[t] = v;
    __syncthreads();
    for (int o = 512; o > 0; o >>= 1) {
        if (t < o) sd[t] += sd[t + o];
        __syncthreads();
    }
    if (t == 0) g_bsum[blockIdx.x] = sd[0];
}

// scanB: exclusive scan of block sums (tiny)
__global__ void k_scanB(int nb) {
    if (threadIdx.x == 0 && blockIdx.x == 0) {
        int acc = 0;
        for (int i = 0; i < nb; i++) { int s = g_bsum[i]; g_bsum[i] = acc; acc += s; }
    }
}

// scanC: per-block exclusive scan + block offset -> rowptr + cursor
__global__ void k_scanC(int E) {
    __shared__ int sd[1024];
    int t = threadIdx.x;
    int base = blockIdx.x * 2048;
    int i0 = base + 2 * t;
    int v0 = (i0 < NN)     ? g_cnt[i0]     : 0;
    int v1 = (i0 + 1 < NN) ? g_cnt[i0 + 1] : 0;
    int tsum = v0 + v1;
    sd[t] = tsum;
    __syncthreads();
    for (int off = 1; off < 1024; off <<= 1) {
        int xval = (t >= off) ? sd[t - off] : 0;
        __syncthreads();
        sd[t] += xval;
        __syncthreads();
    }
    int excl = sd[t] - tsum + g_bsum[blockIdx.x];
    if (i0 < NN)     { g_rowptr[i0]     = excl;      g_cnt[i0]     = excl; }
    if (i0 + 1 < NN) { g_rowptr[i0 + 1] = excl + v0; g_cnt[i0 + 1] = excl + v0; }
    if (blockIdx.x == 0 && t == 0) g_rowptr[NN] = E;
}

__global__ void k_scatter(const int* __restrict__ rows, const int* __restrict__ cols,
                          const float* __restrict__ vals, int E) {
    int e = blockIdx.x * blockDim.x + threadIdx.x;
    if (e >= E) return;
    int r = rows[e];
    int pos = atomicAdd(&g_cnt[r], 1);
    g_edge[pos] = make_int2(cols[e], __float_as_int(vals[e]));
}

// ---------------- MLP: local = tanh(x @ w1^T) @ w2^T ----------------
// w1 stored feature-major with stride 516 (conflict-free LDS.128 phases),
// x broadcast via LDS.128 -> FFMA-bound inner loop.
#define W1S     516
#define SM_W1   (64 * W1S)
#define SM_W2   (64 * 32)
#define SM_XS   (32 * 512)
#define SM_HS   (32 * 64)
#define MLP_SMEM_BYTES ((SM_W1 + SM_W2 + SM_XS + SM_HS) * 4)

__global__ void __launch_bounds__(256, 1)
k_mlp(const float* __restrict__ x, const float* __restrict__ w1,
      const float* __restrict__ w2, int ntiles) {
    extern __shared__ float sm[];
    float* w1s = sm;                 // [64][516]  w1s[j*W1S+k] = w1[j][k]
    float* w2t = sm + SM_W1;         // [64][32]   w2t[j*32+c]  = w2[c][j]
    float* xs  = w2t + SM_W2;        // [32][512]
    float* hs  = xs + SM_XS;         // [32][64]

    int tid  = threadIdx.x;
    int warp = tid >> 5;
    int lane = tid & 31;

    for (int idx = tid; idx < HH * FF; idx += 256) {
        int j = idx >> 9, k = idx & 511;
        w1s[j * W1S + k] = w1[idx];
    }
    for (int idx = tid; idx < CC * HH; idx += 256) {
        int c = idx >> 6, j = idx & 63;
        w2t[j * 32 + c] = w2[idx];
    }
    __syncthreads();

    const float4* wlo4 = (const float4*)(w1s + lane * W1S);
    const float4* whi4 = (const float4*)(w1s + (lane + 32) * W1S);

    for (int tile = blockIdx.x; tile < ntiles; tile += gridDim.x) {
        int rowbase = tile * 32 + warp * 4;

        // load 4 rows of x (coalesced float4)
        #pragma unroll
        for (int r = 0; r < 4; r++) {
            int row = rowbase + r;
            float4* dst = (float4*)(xs + (warp * 4 + r) * 512);
            if (row < NN) {
                const float4* src = (const float4*)(x + (size_t)row * 512);
                #pragma unroll
                for (int i = 0; i < 4; i++) dst[i * 32 + lane] = src[i * 32 + lane];
            } else {
                float4 z = make_float4(0.f, 0.f, 0.f, 0.f);
                #pragma unroll
                for (int i = 0; i < 4; i++) dst[i * 32 + lane] = z;
            }
        }
        __syncwarp();

        float acc[4][2] = {};
        const float4* x0 = (const float4*)(xs + (warp * 4 + 0) * 512);
        const float4* x1 = (const float4*)(xs + (warp * 4 + 1) * 512);
        const float4* x2 = (const float4*)(xs + (warp * 4 + 2) * 512);
        const float4* x3 = (const float4*)(xs + (warp * 4 + 3) * 512);

        #pragma unroll 2
        for (int kk = 0; kk < 128; kk++) {
            float4 wl = wlo4[kk];
            float4 wh = whi4[kk];
            float4 xv;
            xv = x0[kk];
            acc[0][0] = fmaf(xv.x, wl.x, fmaf(xv.y, wl.y, fmaf(xv.z, wl.z, fmaf(xv.w, wl.w, acc[0][0]))));
            acc[0][1] = fmaf(xv.x, wh.x, fmaf(xv.y, wh.y, fmaf(xv.z, wh.z, fmaf(xv.w, wh.w, acc[0][1]))));
            xv = x1[kk];
            acc[1][0] = fmaf(xv.x, wl.x, fmaf(xv.y, wl.y, fmaf(xv.z, wl.z, fmaf(xv.w, wl.w, acc[1][0]))));
            acc[1][1] = fmaf(xv.x, wh.x, fmaf(xv.y, wh.y, fmaf(xv.z, wh.z, fmaf(xv.w, wh.w, acc[1][1]))));
            xv = x2[kk];
            acc[2][0] = fmaf(xv.x, wl.x, fmaf(xv.y, wl.y, fmaf(xv.z, wl.z, fmaf(xv.w, wl.w, acc[2][0]))));
            acc[2][1] = fmaf(xv.x, wh.x, fmaf(xv.y, wh.y, fmaf(xv.z, wh.z, fmaf(xv.w, wh.w, acc[2][1]))));
            xv = x3[kk];
            acc[3][0] = fmaf(xv.x, wl.x, fmaf(xv.y, wl.y, fmaf(xv.z, wl.z, fmaf(xv.w, wl.w, acc[3][0]))));
            acc[3][1] = fmaf(xv.x, wh.x, fmaf(xv.y, wh.y, fmaf(xv.z, wh.z, fmaf(xv.w, wh.w, acc[3][1]))));
        }

        #pragma unroll
        for (int r = 0; r < 4; r++) {
            hs[(warp * 4 + r) * 64 + lane]      = tanhf(acc[r][0]);
            hs[(warp * 4 + r) * 64 + lane + 32] = tanhf(acc[r][1]);
        }
        __syncwarp();

        #pragma unroll
        for (int r = 0; r < 4; r++) {
            int row = rowbase + r;
            if (row < NN) {
                const float* hrow = hs + (warp * 4 + r) * 64;
                float a = 0.f;
                #pragma unroll
                for (int j = 0; j < 64; j++)
                    a = fmaf(hrow[j], w2t[j * 32 + lane], a);
                g_local_h[(size_t)row * 32 + lane] = __float2half(a);
            }
        }
        __syncwarp();
    }
}

// ---------------- SpMM: pout = A_hat @ pin + ALPHA * local ----------------
// Warp per row, split into 2 half-warps processing 2 edges at a time.
// Each lane gathers a __half2 (2 features): 16 lanes x 4B = 64B per row gather.
// Edge (col,val) fetched as int2 via near-uniform LDG (2 addrs -> 1 sector, L1-hot).
__device__ __forceinline__ float2
spmm_row(const __half* __restrict__ pin, int row, int lane) {
    int s = g_rowptr[row];
    int e = g_rowptr[row + 1];
    int half_id = lane >> 4;       // 0: even edges, 1: odd edges
    int fpair   = lane & 15;       // feature pair index (features 2f, 2f+1)

    float ax = 0.f, ay = 0.f;
    for (int t = s; t < e; t += 8) {
        int   cols[4];
        float vals[4];
        #pragma unroll
        for (int u = 0; u < 4; u++) {
            int tt = t + 2 * u + half_id;
            int2 ed = (tt < e) ? g_edge[tt] : make_int2(0, 0);
            cols[u] = ed.x;
            vals[u] = __int_as_float(ed.y);
        }
        float2 pf[4];
        #pragma unroll
        for (int u = 0; u < 4; u++) {
            __half2 ph = *(const __half2*)(pin + (size_t)cols[u] * 32 + fpair * 2);
            pf[u] = __half22float2(ph);
        }
        #pragma unroll
        for (int u = 0; u < 4; u++) {
            ax = fmaf(vals[u], pf[u].x, ax);
            ay = fmaf(vals[u], pf[u].y, ay);
        }
    }
    // combine the two half-warp partial sums (full sum lands in all lanes)
    ax += __shfl_xor_sync(0xffffffffu, ax, 16);
    ay += __shfl_xor_sync(0xffffffffu, ay, 16);

    __half2 lh = *(const __half2*)(g_local_h + (size_t)row * 32 + fpair * 2);
    float2 lf = __half22float2(lh);
    return make_float2(fmaf(ALPHA_F, lf.x, ax), fmaf(ALPHA_F, lf.y, ay));
}

__global__ void __launch_bounds__(256)
k_spmm_h(const __half* __restrict__ pin, __half* __restrict__ pout) {
    int gw = (blockIdx.x * blockDim.x + threadIdx.x) >> 5;
    if (gw >= NN) return;
    int lane = threadIdx.x & 31;
    float2 r = spmm_row(pin, gw, lane);
    if (lane < 16)
        *(__half2*)(pout + (size_t)gw * 32 + lane * 2) = __floats2half2_rn(r.x, r.y);
}

__global__ void __launch_bounds__(256)
k_spmm_f(const __half* __restrict__ pin, float* __restrict__ pout) {
    int gw = (blockIdx.x * blockDim.x + threadIdx.x) >> 5;
    if (gw >= NN) return;
    int lane = threadIdx.x & 31;
    float2 r = spmm_row(pin, gw, lane);
    if (lane < 16)
        *(float2*)(pout + (size_t)gw * 32 + lane * 2) = r;
}

// ---------------- launch ----------------
extern "C" void kernel_launch(void* const* d_in, const int* in_sizes, int n_in,
                              void* d_out, int out_size) {
    const float* x    = (const float*)d_in[0];
    const float* w1   = (const float*)d_in[1];
    const float* w2   = (const float*)d_in[2];
    const int*   rows = (const int*)d_in[3];
    const int*   cols = (const int*)d_in[4];
    const float* vals = (const float*)d_in[5];
    float*       out  = (float*)d_out;

    int E = in_sizes[3];
    if (E > EE) E = EE;

    // CSR build
    k_zero_cnt<<<(NN + 255) / 256, 256>>>();
    k_hist<<<(E + 255) / 256, 256>>>(rows, E);
    int nb = (NN + 2047) / 2048;  // 49
    k_scanA<<<nb, 1024>>>();
    k_scanB<<<1, 32>>>(nb);
    k_scanC<<<nb, 1024>>>(E);
    k_scatter<<<(E + 255) / 256, 256>>>(rows, cols, vals, E);

    // MLP
    cudaFuncSetAttribute(k_mlp, cudaFuncAttributeMaxDynamicSharedMemorySize, MLP_SMEM_BYTES);
    int ntiles = (NN + 31) / 32;
    k_mlp<<<296, 256, MLP_SMEM_BYTES>>>(x, w1, w2, ntiles);

    // power iterations (ping-pong, last one straight into d_out)
    __half *pA, *pB, *plocal;
    cudaGetSymbolAddress((void**)&pA, g_pA);
    cudaGetSymbolAddress((void**)&pB, g_pB);
    cudaGetSymbolAddress((void**)&plocal, g_local_h);

    const __half* pin = plocal;
    int grid = (NN * 32 + 255) / 256;  // warp per row
    for (int i = 0; i < NITER; i++) {
        if (i == NITER - 1) {
            k_spmm_f<<<grid, 256>>>(pin, out);
        } else {
            __half* po = (i & 1) ? pB : pA;
            k_spmm_h<<<grid, 256>>>(pin, po);
            pin = po;
        }
    }
}

// round 3
// speedup vs baseline: 1.6163x; 1.3530x over previous
#include <cuda_runtime.h>
#include <cuda_fp16.h>
#include <math.h>
#include <stdint.h>

#define NN      100000
#define FF      512
#define HH      64
#define CC      32
#define EE      3300000
#define ALPHA_F 0.1f
#define NITER   10

// ---------------- device scratch (allocation-free) ----------------
__device__ int    g_cnt[NN];
__device__ int    g_rowptr[NN + 1];
__device__ int    g_cole[EE];                 // col-only edges (4B)
__device__ float  g_rs[NN];                   // rsqrt(deg)
__device__ __half g_local_h[(size_t)NN * CC];
__device__ __half g_pA[(size_t)NN * CC];
__device__ __half g_pB[(size_t)NN * CC];
__device__ int    g_bsum[64];

// ---------------- CSR build ----------------
__global__ void k_zero_cnt() {
    int i = blockIdx.x * blockDim.x + threadIdx.x;
    if (i < NN) g_cnt[i] = 0;
}

__global__ void k_hist(const int* __restrict__ rows, int E) {
    int e = blockIdx.x * blockDim.x + threadIdx.x;
    if (e < E) atomicAdd(&g_cnt[rows[e]], 1);
}

__global__ void k_scanA() {
    __shared__ int sd[1024];
    int t = threadIdx.x;
    int i0 = blockIdx.x * 2048 + 2 * t;
    int v = 0;
    if (i0 < NN)     v += g_cnt[i0];
    if (i0 + 1 < NN) v += g_cnt[i0 + 1];
    sd[t] = v;
    __syncthreads();
    for (int o = 512; o > 0; o >>= 1) {
        if (t < o) sd[t] += sd[t + o];
        __syncthreads();
    }
    if (t == 0) g_bsum[blockIdx.x] = sd[0];
}

__global__ void k_scanB(int nb) {
    if (threadIdx.x == 0 && blockIdx.x == 0) {
        int acc = 0;
        for (int i = 0; i < nb; i++) { int s = g_bsum[i]; g_bsum[i] = acc; acc += s; }
    }
}

// per-block exclusive scan + write rowptr/cursor + rs = rsqrt(deg)
__global__ void k_scanC(int E) {
    __shared__ int sd[1024];
    int t = threadIdx.x;
    int i0 = blockIdx.x * 2048 + 2 * t;
    int v0 = (i0 < NN)     ? g_cnt[i0]     : 0;
    int v1 = (i0 + 1 < NN) ? g_cnt[i0 + 1] : 0;
    int tsum = v0 + v1;
    sd[t] = tsum;
    __syncthreads();
    for (int off = 1; off < 1024; off <<= 1) {
        int xval = (t >= off) ? sd[t - off] : 0;
        __syncthreads();
        sd[t] += xval;
        __syncthreads();
    }
    int excl = sd[t] - tsum + g_bsum[blockIdx.x];
    if (i0 < NN) {
        g_rowptr[i0] = excl;  g_cnt[i0] = excl;
        g_rs[i0] = rsqrtf((float)(v0 > 0 ? v0 : 1));
    }
    if (i0 + 1 < NN) {
        g_rowptr[i0 + 1] = excl + v0;  g_cnt[i0 + 1] = excl + v0;
        g_rs[i0 + 1] = rsqrtf((float)(v1 > 0 ? v1 : 1));
    }
    if (blockIdx.x == 0 && t == 0) g_rowptr[NN] = E;
}

__global__ void k_scatter(const int* __restrict__ rows, const int* __restrict__ cols, int E) {
    int e = blockIdx.x * blockDim.x + threadIdx.x;
    if (e >= E) return;
    int pos = atomicAdd(&g_cnt[rows[e]], 1);
    g_cole[pos] = cols[e];
}

// ---------------- MLP via mma.sync tf32 ----------------
// local = tanh(x @ w1^T) @ w2^T, stored fp16.
// Per CTA: 128 rows. K chunked x64. Warp grid 4m x 2n.
// SMEM strides padded for conflict-free fragment LDS:
//   A-pattern (addr = r*S + k): S=68 -> bank = 4*gid + tid, all unique.
//   B-pattern (addr = n*S + k): S=68 -> bank = 4*gid + tid, all unique.

#define XS_S 68
#define MLP_SMEM_BYTES ((128*68 + 64*68 + 32*68) * 4)

__device__ __forceinline__ uint32_t f2tf32(float f) {
    uint32_t u;
    asm("cvt.rna.tf32.f32 %0, %1;" : "=r"(u) : "f"(f));
    return u;
}

__device__ __forceinline__ void mma_tf32(float* c, const uint32_t* a, const uint32_t* b) {
    asm volatile(
        "mma.sync.aligned.m16n8k8.row.col.f32.tf32.tf32.f32 "
        "{%0,%1,%2,%3}, {%4,%5,%6,%7}, {%8,%9}, {%0,%1,%2,%3};"
        : "+f"(c[0]), "+f"(c[1]), "+f"(c[2]), "+f"(c[3])
        : "r"(a[0]), "r"(a[1]), "r"(a[2]), "r"(a[3]), "r"(b[0]), "r"(b[1]));
}

__global__ void __launch_bounds__(256, 2)
k_mlp_mma(const float* __restrict__ x, const float* __restrict__ w1,
          const float* __restrict__ w2) {
    extern __shared__ uint32_t sm[];
    uint32_t* xs  = sm;                      // [128][68] x chunk / later h
    uint32_t* wn1 = sm + 128 * XS_S;         // [64][68]  w1 chunk  [n][k]
    uint32_t* ws2 = wn1 + 64 * XS_S;         // [32][68]  w2        [n][k]

    int tid  = threadIdx.x;
    int warp = tid >> 5;
    int lane = tid & 31;
    int gid  = lane >> 2;       // 0..7
    int tg   = lane & 3;        // 0..3
    int wm   = warp >> 1;       // 0..3  (32-row slab)
    int wn   = warp & 1;        // 0..1  (32-col slab of h)
    int rowbase = blockIdx.x * 128;

    // load w2 (once): [32][64] -> ws2[n*68 + k]
    #pragma unroll
    for (int i = 0; i < 2; i++) {
        int idx = i * 256 + tid;            // 0..511 float4
        int n = idx >> 4, c4 = (idx & 15) * 4;
        float4 v = *(const float4*)(w2 + n * 64 + c4);
        uint32_t* d = ws2 + n * XS_S + c4;
        d[0] = f2tf32(v.x); d[1] = f2tf32(v.y); d[2] = f2tf32(v.z); d[3] = f2tf32(v.w);
    }

    float acc[2][4][4];
    #pragma unroll
    for (int mt = 0; mt < 2; mt++)
        #pragma unroll
        for (int nt = 0; nt < 4; nt++)
            #pragma unroll
            for (int i = 0; i < 4; i++) acc[mt][nt][i] = 0.f;

    for (int ck = 0; ck < 8; ck++) {
        int kb = ck * 64;
        // load x chunk [128][64]
        #pragma unroll
        for (int i = 0; i < 8; i++) {
            int idx = i * 256 + tid;        // 0..2047 float4
            int row = idx >> 4, c4 = (idx & 15) * 4;
            float4 v = make_float4(0.f, 0.f, 0.f, 0.f);
            if (rowbase + row < NN)
                v = *(const float4*)(x + (size_t)(rowbase + row) * 512 + kb + c4);
            uint32_t* d = xs + row * XS_S + c4;
            d[0] = f2tf32(v.x); d[1] = f2tf32(v.y); d[2] = f2tf32(v.z); d[3] = f2tf32(v.w);
        }
        // load w1 chunk [64][64]
        #pragma unroll
        for (int i = 0; i < 4; i++) {
            int idx = i * 256 + tid;        // 0..1023 float4
            int n = idx >> 4, c4 = (idx & 15) * 4;
            float4 v = *(const float4*)(w1 + (size_t)n * 512 + kb + c4);
            uint32_t* d = wn1 + n * XS_S + c4;
            d[0] = f2tf32(v.x); d[1] = f2tf32(v.y); d[2] = f2tf32(v.z); d[3] = f2tf32(v.w);
        }
        __syncthreads();

        #pragma unroll
        for (int ks = 0; ks < 8; ks++) {
            int k0 = ks * 8;
            uint32_t a[2][4];
            #pragma unroll
            for (int mt = 0; mt < 2; mt++) {
                int r0 = wm * 32 + mt * 16;
                a[mt][0] = xs[(r0 + gid) * XS_S + k0 + tg];
                a[mt][1] = xs[(r0 + gid + 8) * XS_S + k0 + tg];
                a[mt][2] = xs[(r0 + gid) * XS_S + k0 + tg + 4];
                a[mt][3] = xs[(r0 + gid + 8) * XS_S + k0 + tg + 4];
            }
            uint32_t b[4][2];
            #pragma unroll
            for (int nt = 0; nt < 4; nt++) {
                int n0 = wn * 32 + nt * 8 + gid;
                b[nt][0] = wn1[n0 * XS_S + k0 + tg];
                b[nt][1] = wn1[n0 * XS_S + k0 + tg + 4];
            }
            #pragma unroll
            for (int mt = 0; mt < 2; mt++)
                #pragma unroll
                for (int nt = 0; nt < 4; nt++)
                    mma_tf32(acc[mt][nt], a[mt], b[nt]);
        }
        __syncthreads();
    }

    // tanh -> hs (reuse xs buffer) as tf32 bits
    #pragma unroll
    for (int mt = 0; mt < 2; mt++) {
        int r = wm * 32 + mt * 16 + gid;
        #pragma unroll
        for (int nt = 0; nt < 4; nt++) {
            int c = wn * 32 + nt * 8 + 2 * tg;
            uint2 lo = make_uint2(f2tf32(tanhf(acc[mt][nt][0])), f2tf32(tanhf(acc[mt][nt][1])));
            uint2 hi = make_uint2(f2tf32(tanhf(acc[mt][nt][2])), f2tf32(tanhf(acc[mt][nt][3])));
            *(uint2*)(xs + r * XS_S + c)       = lo;
            *(uint2*)(xs + (r + 8) * XS_S + c) = hi;
        }
    }
    __syncthreads();

    // layer 2: h[128][64] @ w2^T -> [128][32]
    float acc2[2][2][4];
    #pragma unroll
    for (int mt = 0; mt < 2; mt++)
        #pragma unroll
        for (int nt = 0; nt < 2; nt++)
            #pragma unroll
            for (int i = 0; i < 4; i++) acc2[mt][nt][i] = 0.f;

    #pragma unroll
    for (int ks = 0; ks < 8; ks++) {
        int k0 = ks * 8;
        uint32_t a[2][4];
        #pragma unroll
        for (int mt = 0; mt < 2; mt++) {
            int r0 = wm * 32 + mt * 16;
            a[mt][0] = xs[(r0 + gid) * XS_S + k0 + tg];
            a[mt][1] = xs[(r0 + gid + 8) * XS_S + k0 + tg];
            a[mt][2] = xs[(r0 + gid) * XS_S + k0 + tg + 4];
            a[mt][3] = xs[(r0 + gid + 8) * XS_S + k0 + tg + 4];
        }
        uint32_t b[2][2];
        #pragma unroll
        for (int nt = 0; nt < 2; nt++) {
            int n0 = wn * 16 + nt * 8 + gid;
            b[nt][0] = ws2[n0 * XS_S + k0 + tg];
            b[nt][1] = ws2[n0 * XS_S + k0 + tg + 4];
        }
        #pragma unroll
        for (int mt = 0; mt < 2; mt++)
            #pragma unroll
            for (int nt = 0; nt < 2; nt++)
                mma_tf32(acc2[mt][nt], a[mt], b[nt]);
    }

    // store local (fp16)
    #pragma unroll
    for (int mt = 0; mt < 2; mt++) {
        int r = rowbase + wm * 32 + mt * 16 + gid;
        #pragma unroll
        for (int nt = 0; nt < 2; nt++) {
            int c = wn * 16 + nt * 8 + 2 * tg;
            if (r < NN)
                *(__half2*)(g_local_h + (size_t)r * 32 + c) =
                    __floats2half2_rn(acc2[mt][nt][0], acc2[mt][nt][1]);
            if (r + 8 < NN)
                *(__half2*)(g_local_h + (size_t)(r + 8) * 32 + c) =
                    __floats2half2_rn(acc2[mt][nt][2], acc2[mt][nt][3]);
        }
    }
}

// ---------------- SpMM on scaled p (q = p * rs) ----------------
// out_r = (1-a)*rs[r]*sum_{e in row} q[col_e] + a*local[r];  q_next = out*rs
__device__ __forceinline__ float2
spmm_row(const __half* __restrict__ pin, int row, int lane) {
    int s = g_rowptr[row];
    int e = g_rowptr[row + 1];
    int half_id = lane >> 4;
    int fpair   = lane & 15;

    float ax = 0.f, ay = 0.f;
    for (int t = s; t < e; t += 16) {
        int   cols[8];
        float msk[8];
        #pragma unroll
        for (int u = 0; u < 8; u++) {
            int tt = t + 2 * u + half_id;
            bool ok = (tt < e);
            cols[u] = ok ? g_cole[tt] : 0;
            msk[u]  = ok ? 1.f : 0.f;
        }
        float2 pf[8];
        #pragma unroll
        for (int u = 0; u < 8; u++) {
            __half2 ph = *(const __half2*)(pin + (size_t)cols[u] * 32 + fpair * 2);
            pf[u] = __half22float2(ph);
        }
        #pragma unroll
        for (int u = 0; u < 8; u++) {
            ax = fmaf(msk[u], pf[u].x, ax);
            ay = fmaf(msk[u], pf[u].y, ay);
        }
    }
    ax += __shfl_xor_sync(0xffffffffu, ax, 16);
    ay += __shfl_xor_sync(0xffffffffu, ay, 16);

    float w = (1.0f - ALPHA_F) * g_rs[row];
    __half2 lh = *(const __half2*)(g_local_h + (size_t)row * 32 + fpair * 2);
    float2 lf = __half22float2(lh);
    return make_float2(fmaf(w, ax, ALPHA_F * lf.x), fmaf(w, ay, ALPHA_F * lf.y));
}

__global__ void __launch_bounds__(256)
k_spmm_h(const __half* __restrict__ pin, __half* __restrict__ pout) {
    int gw = (blockIdx.x * blockDim.x + threadIdx.x) >> 5;
    if (gw >= NN) return;
    int lane = threadIdx.x & 31;
    float2 r = spmm_row(pin, gw, lane);
    if (lane < 16) {
        float rs = g_rs[gw];
        *(__half2*)(pout + (size_t)gw * 32 + lane * 2) =
            __floats2half2_rn(r.x * rs, r.y * rs);
    }
}

__global__ void __launch_bounds__(256)
k_spmm_f(const __half* __restrict__ pin, float* __restrict__ pout) {
    int gw = (blockIdx.x * blockDim.x + threadIdx.x) >> 5;
    if (gw >= NN) return;
    int lane = threadIdx.x & 31;
    float2 r = spmm_row(pin, gw, lane);
    if (lane < 16)
        *(float2*)(pout + (size_t)gw * 32 + lane * 2) = r;
}

// seed: q0 = local * rs (scan starts from p = local)
__global__ void k_seed(__half* __restrict__ q) {
    int i = blockIdx.x * blockDim.x + threadIdx.x;
    if (i >= NN * 16) return;
    int row = i >> 4, fp = i & 15;
    float rs = g_rs[row];
    __half2 lh = *(const __half2*)(g_local_h + (size_t)row * 32 + fp * 2);
    float2 lf = __half22float2(lh);
    *(__half2*)(q + (size_t)row * 32 + fp * 2) = __floats2half2_rn(lf.x * rs, lf.y * rs);
}

// ---------------- launch ----------------
extern "C" void kernel_launch(void* const* d_in, const int* in_sizes, int n_in,
                              void* d_out, int out_size) {
    const float* x    = (const float*)d_in[0];
    const float* w1   = (const float*)d_in[1];
    const float* w2   = (const float*)d_in[2];
    const int*   rows = (const int*)d_in[3];
    const int*   cols = (const int*)d_in[4];
    float*       out  = (float*)d_out;

    int E = in_sizes[3];
    if (E > EE) E = EE;

    // CSR build
    k_zero_cnt<<<(NN + 255) / 256, 256>>>();
    k_hist<<<(E + 255) / 256, 256>>>(rows, E);
    int nb = (NN + 2047) / 2048;
    k_scanA<<<nb, 1024>>>();
    k_scanB<<<1, 32>>>(nb);
    k_scanC<<<nb, 1024>>>(E);
    k_scatter<<<(E + 255) / 256, 256>>>(rows, cols, E);

    // MLP (tensor cores)
    cudaFuncSetAttribute(k_mlp_mma, cudaFuncAttributeMaxDynamicSharedMemorySize, MLP_SMEM_BYTES);
    k_mlp_mma<<<(NN + 127) / 128, 256, MLP_SMEM_BYTES>>>(x, w1, w2);

    // seed q0 = local * rs
    __half *pA, *pB;
    cudaGetSymbolAddress((void**)&pA, g_pA);
    cudaGetSymbolAddress((void**)&pB, g_pB);
    k_seed<<<(NN * 16 + 255) / 256, 256>>>(pB);

    const __half* pin = pB;
    int grid = (NN * 32 + 255) / 256;
    for (int i = 0; i < NITER; i++) {
        if (i == NITER - 1) {
            k_spmm_f<<<grid, 256>>>(pin, out);
        } else {
            __half* po = (i & 1) ? pA : pB;      // alternate; i=0 writes pA
            po = (i & 1) ? pB : pA;
            k_spmm_h<<<grid, 256>>>(pin, po);
            pin = po;
        }
    }
}

// round 4
// speedup vs baseline: 1.7206x; 1.0645x over previous
#include <cuda_runtime.h>
#include <cuda_fp16.h>
#include <math.h>
#include <stdint.h>

#define NN      100000
#define FF      512
#define HH      64
#define CC      32
#define EE      3300000
#define ALPHA_F 0.1f
#define NITER   10

// ---------------- device scratch (allocation-free) ----------------
__device__ int    g_cnt[NN];
__device__ int    g_rowptr[NN + 1];
__device__ __align__(16) int g_cole[EE + 16];   // col-only edges, padded
__device__ float  g_rs[NN];                     // rsqrt(deg)
__device__ __half g_local_h[(size_t)NN * CC];
__device__ __half g_pA[(size_t)(NN + 1) * CC];  // row NN = zero sentinel
__device__ __half g_pB[(size_t)(NN + 1) * CC];
__device__ int    g_bsum[64];

// ---------------- CSR build ----------------
__global__ void k_zero_cnt() {
    int i = blockIdx.x * blockDim.x + threadIdx.x;
    if (i < NN) g_cnt[i] = 0;
}

__global__ void k_hist(const int* __restrict__ rows, int E) {
    int e = blockIdx.x * blockDim.x + threadIdx.x;
    if (e < E) atomicAdd(&g_cnt[rows[e]], 1);
}

__global__ void k_scanA() {
    __shared__ int sd[1024];
    int t = threadIdx.x;
    int i0 = blockIdx.x * 2048 + 2 * t;
    int v = 0;
    if (i0 < NN)     v += g_cnt[i0];
    if (i0 + 1 < NN) v += g_cnt[i0 + 1];
    sd[t] = v;
    __syncthreads();
    for (int o = 512; o > 0; o >>= 1) {
        if (t < o) sd[t] += sd[t + o];
        __syncthreads();
    }
    if (t == 0) g_bsum[blockIdx.x] = sd[0];
}

__global__ void k_scanB(int nb) {
    if (threadIdx.x == 0 && blockIdx.x == 0) {
        int acc = 0;
        for (int i = 0; i < nb; i++) { int s = g_bsum[i]; g_bsum[i] = acc; acc += s; }
    }
}

__global__ void k_scanC(int E) {
    __shared__ int sd[1024];
    int t = threadIdx.x;
    int i0 = blockIdx.x * 2048 + 2 * t;
    int v0 = (i0 < NN)     ? g_cnt[i0]     : 0;
    int v1 = (i0 + 1 < NN) ? g_cnt[i0 + 1] : 0;
    int tsum = v0 + v1;
    sd[t] = tsum;
    __syncthreads();
    for (int off = 1; off < 1024; off <<= 1) {
        int xval = (t >= off) ? sd[t - off] : 0;
        __syncthreads();
        sd[t] += xval;
        __syncthreads();
    }
    int excl = sd[t] - tsum + g_bsum[blockIdx.x];
    if (i0 < NN) {
        g_rowptr[i0] = excl;  g_cnt[i0] = excl;
        g_rs[i0] = rsqrtf((float)(v0 > 0 ? v0 : 1));
    }
    if (i0 + 1 < NN) {
        g_rowptr[i0 + 1] = excl + v0;  g_cnt[i0 + 1] = excl + v0;
        g_rs[i0 + 1] = rsqrtf((float)(v1 > 0 ? v1 : 1));
    }
    if (blockIdx.x == 0 && t == 0) g_rowptr[NN] = E;
}

__global__ void k_scatter(const int* __restrict__ rows, const int* __restrict__ cols, int E) {
    int e = blockIdx.x * blockDim.x + threadIdx.x;
    if (e >= E) return;
    int pos = atomicAdd(&g_cnt[rows[e]], 1);
    g_cole[pos] = cols[e];
}

// ---------------- MLP via mma.sync tf32 ----------------
#define XS_S 68
#define MLP_SMEM_BYTES ((128*68 + 64*68 + 32*68) * 4)

__device__ __forceinline__ uint32_t f2tf32(float f) {
    uint32_t u;
    asm("cvt.rna.tf32.f32 %0, %1;" : "=r"(u) : "f"(f));
    return u;
}

__device__ __forceinline__ void mma_tf32(float* c, const uint32_t* a, const uint32_t* b) {
    asm volatile(
        "mma.sync.aligned.m16n8k8.row.col.f32.tf32.tf32.f32 "
        "{%0,%1,%2,%3}, {%4,%5,%6,%7}, {%8,%9}, {%0,%1,%2,%3};"
        : "+f"(c[0]), "+f"(c[1]), "+f"(c[2]), "+f"(c[3])
        : "r"(a[0]), "r"(a[1]), "r"(a[2]), "r"(a[3]), "r"(b[0]), "r"(b[1]));
}

__global__ void __launch_bounds__(256, 2)
k_mlp_mma(const float* __restrict__ x, const float* __restrict__ w1,
          const float* __restrict__ w2) {
    extern __shared__ uint32_t sm[];
    uint32_t* xs  = sm;                      // [128][68] x chunk / later h
    uint32_t* wn1 = sm + 128 * XS_S;         // [64][68]  w1 chunk [n][k]
    uint32_t* ws2 = wn1 + 64 * XS_S;         // [32][68]  w2       [n][k]

    int tid  = threadIdx.x;
    int warp = tid >> 5;
    int lane = tid & 31;
    int gid  = lane >> 2;
    int tg   = lane & 3;
    int wm   = warp >> 1;
    int wn   = warp & 1;
    int rowbase = blockIdx.x * 128;

    // load w2 once
    #pragma unroll
    for (int i = 0; i < 2; i++) {
        int idx = i * 256 + tid;
        int n = idx >> 4, c4 = (idx & 15) * 4;
        float4 v = *(const float4*)(w2 + n * 64 + c4);
        uint32_t* d = ws2 + n * XS_S + c4;
        d[0] = f2tf32(v.x); d[1] = f2tf32(v.y); d[2] = f2tf32(v.z); d[3] = f2tf32(v.w);
    }

    // per-thread x-prefetch coordinates (8 float4 per thread per chunk)
    int xrow[8], xc4[8];
    #pragma unroll
    for (int i = 0; i < 8; i++) {
        int idx = i * 256 + tid;
        xrow[i] = idx >> 4;
        xc4[i]  = (idx & 15) * 4;
    }

    float4 xf[8];
    // prefetch chunk 0
    #pragma unroll
    for (int i = 0; i < 8; i++) {
        xf[i] = make_float4(0.f, 0.f, 0.f, 0.f);
        if (rowbase + xrow[i] < NN)
            xf[i] = *(const float4*)(x + (size_t)(rowbase + xrow[i]) * 512 + xc4[i]);
    }

    float acc[2][4][4];
    #pragma unroll
    for (int mt = 0; mt < 2; mt++)
        #pragma unroll
        for (int nt = 0; nt < 4; nt++)
            #pragma unroll
            for (int i = 0; i < 4; i++) acc[mt][nt][i] = 0.f;

    for (int ck = 0; ck < 8; ck++) {
        int kb = ck * 64;
        // store prefetched x to smem (cvt to tf32)
        #pragma unroll
        for (int i = 0; i < 8; i++) {
            uint32_t* d = xs + xrow[i] * XS_S + xc4[i];
            d[0] = f2tf32(xf[i].x); d[1] = f2tf32(xf[i].y);
            d[2] = f2tf32(xf[i].z); d[3] = f2tf32(xf[i].w);
        }
        // w1 chunk (L2-hot after first CTAs)
        #pragma unroll
        for (int i = 0; i < 4; i++) {
            int idx = i * 256 + tid;
            int n = idx >> 4, c4 = (idx & 15) * 4;
            float4 v = *(const float4*)(w1 + (size_t)n * 512 + kb + c4);
            uint32_t* d = wn1 + n * XS_S + c4;
            d[0] = f2tf32(v.x); d[1] = f2tf32(v.y); d[2] = f2tf32(v.z); d[3] = f2tf32(v.w);
        }
        __syncthreads();

        // prefetch next chunk while tensor pipe works
        if (ck < 7) {
            int kb2 = kb + 64;
            #pragma unroll
            for (int i = 0; i < 8; i++) {
                if (rowbase + xrow[i] < NN)
                    xf[i] = *(const float4*)(x + (size_t)(rowbase + xrow[i]) * 512 + kb2 + xc4[i]);
            }
        }

        #pragma unroll
        for (int ks = 0; ks < 8; ks++) {
            int k0 = ks * 8;
            uint32_t a[2][4];
            #pragma unroll
            for (int mt = 0; mt < 2; mt++) {
                int r0 = wm * 32 + mt * 16;
                a[mt][0] = xs[(r0 + gid) * XS_S + k0 + tg];
                a[mt][1] = xs[(r0 + gid + 8) * XS_S + k0 + tg];
                a[mt][2] = xs[(r0 + gid) * XS_S + k0 + tg + 4];
                a[mt][3] = xs[(r0 + gid + 8) * XS_S + k0 + tg + 4];
            }
            uint32_t b[4][2];
            #pragma unroll
            for (int nt = 0; nt < 4; nt++) {
                int n0 = wn * 32 + nt * 8 + gid;
                b[nt][0] = wn1[n0 * XS_S + k0 + tg];
                b[nt][1] = wn1[n0 * XS_S + k0 + tg + 4];
            }
            #pragma unroll
            for (int mt = 0; mt < 2; mt++)
                #pragma unroll
                for (int nt = 0; nt < 4; nt++)
                    mma_tf32(acc[mt][nt], a[mt], b[nt]);
        }
        __syncthreads();
    }

    // tanh -> h in xs (tf32 bits)
    #pragma unroll
    for (int mt = 0; mt < 2; mt++) {
        int r = wm * 32 + mt * 16 + gid;
        #pragma unroll
        for (int nt = 0; nt < 4; nt++) {
            int c = wn * 32 + nt * 8 + 2 * tg;
            uint2 lo = make_uint2(f2tf32(tanhf(acc[mt][nt][0])), f2tf32(tanhf(acc[mt][nt][1])));
            uint2 hi = make_uint2(f2tf32(tanhf(acc[mt][nt][2])), f2tf32(tanhf(acc[mt][nt][3])));
            *(uint2*)(xs + r * XS_S + c)       = lo;
            *(uint2*)(xs + (r + 8) * XS_S + c) = hi;
        }
    }
    __syncthreads();

    // layer 2: h[128][64] @ w2^T
    float acc2[2][2][4];
    #pragma unroll
    for (int mt = 0; mt < 2; mt++)
        #pragma unroll
        for (int nt = 0; nt < 2; nt++)
            #pragma unroll
            for (int i = 0; i < 4; i++) acc2[mt][nt][i] = 0.f;

    #pragma unroll
    for (int ks = 0; ks < 8; ks++) {
        int k0 = ks * 8;
        uint32_t a[2][4];
        #pragma unroll
        for (int mt = 0; mt < 2; mt++) {
            int r0 = wm * 32 + mt * 16;
            a[mt][0] = xs[(r0 + gid) * XS_S + k0 + tg];
            a[mt][1] = xs[(r0 + gid + 8) * XS_S + k0 + tg];
            a[mt][2] = xs[(r0 + gid) * XS_S + k0 + tg + 4];
            a[mt][3] = xs[(r0 + gid + 8) * XS_S + k0 + tg + 4];
        }
        uint32_t b[2][2];
        #pragma unroll
        for (int nt = 0; nt < 2; nt++) {
            int n0 = wn * 16 + nt * 8 + gid;
            b[nt][0] = ws2[n0 * XS_S + k0 + tg];
            b[nt][1] = ws2[n0 * XS_S + k0 + tg + 4];
        }
        #pragma unroll
        for (int mt = 0; mt < 2; mt++)
            #pragma unroll
            for (int nt = 0; nt < 2; nt++)
                mma_tf32(acc2[mt][nt], a[mt], b[nt]);
    }

    #pragma unroll
    for (int mt = 0; mt < 2; mt++) {
        int r = rowbase + wm * 32 + mt * 16 + gid;
        #pragma unroll
        for (int nt = 0; nt < 2; nt++) {
            int c = wn * 16 + nt * 8 + 2 * tg;
            if (r < NN)
                *(__half2*)(g_local_h + (size_t)r * 32 + c) =
                    __floats2half2_rn(acc2[mt][nt][0], acc2[mt][nt][1]);
            if (r + 8 < NN)
                *(__half2*)(g_local_h + (size_t)(r + 8) * 32 + c) =
                    __floats2half2_rn(acc2[mt][nt][2], acc2[mt][nt][3]);
        }
    }
}

// ---------------- SpMM on scaled p (q = p * rs) ----------------
// Edge stream via aligned int4 (contiguous 8-edge blocks per half-warp);
// out-of-range edges redirected to zero sentinel row NN.
__device__ __forceinline__ float2
spmm_row(const __half* __restrict__ pin, int row, int lane) {
    int s = g_rowptr[row];
    int e = g_rowptr[row + 1];
    int half_id = lane >> 4;
    int fpair   = lane & 15;

    float ax = 0.f, ay = 0.f;

    // scalar head up to 4-alignment (half 0 accumulates)
    int sA = (s + 3) & ~3;
    if (sA > e) sA = e;
    if (half_id == 0) {
        for (int t = s; t < sA; t++) {
            int c = __ldg(&g_cole[t]);
            float2 pf = __half22float2(*(const __half2*)(pin + (size_t)c * 32 + fpair * 2));
            ax += pf.x; ay += pf.y;
        }
    }

    // main: chunks of 16, half h owns [t, t+8) with t = sA + 16*i + 8*h
    for (int t = sA + half_id * 8; t < e; t += 16) {
        const int4* p4 = (const int4*)(g_cole + t);
        int4 c0 = __ldg(p4);
        int4 c1 = __ldg(p4 + 1);
        int cols[8] = {c0.x, c0.y, c0.z, c0.w, c1.x, c1.y, c1.z, c1.w};
        #pragma unroll
        for (int u = 0; u < 8; u++)
            if (t + u >= e) cols[u] = NN;     // sentinel -> zero row
        #pragma unroll
        for (int u = 0; u < 8; u++) {
            float2 pf = __half22float2(*(const __half2*)(pin + (size_t)cols[u] * 32 + fpair * 2));
            ax += pf.x; ay += pf.y;
        }
    }

    ax += __shfl_xor_sync(0xffffffffu, ax, 16);
    ay += __shfl_xor_sync(0xffffffffu, ay, 16);

    float w = (1.0f - ALPHA_F) * g_rs[row];
    float2 lf = __half22float2(*(const __half2*)(g_local_h + (size_t)row * 32 + fpair * 2));
    return make_float2(fmaf(w, ax, ALPHA_F * lf.x), fmaf(w, ay, ALPHA_F * lf.y));
}

__global__ void __launch_bounds__(256)
k_spmm_h(const __half* __restrict__ pin, __half* __restrict__ pout) {
    int gw = (blockIdx.x * blockDim.x + threadIdx.x) >> 5;
    if (gw >= NN) return;
    int lane = threadIdx.x & 31;
    float2 r = spmm_row(pin, gw, lane);
    if (lane < 16) {
        float rs = g_rs[gw];
        *(__half2*)(pout + (size_t)gw * 32 + lane * 2) =
            __floats2half2_rn(r.x * rs, r.y * rs);
    }
}

__global__ void __launch_bounds__(256)
k_spmm_f(const __half* __restrict__ pin, float* __restrict__ pout) {
    int gw = (blockIdx.x * blockDim.x + threadIdx.x) >> 5;
    if (gw >= NN) return;
    int lane = threadIdx.x & 31;
    float2 r = spmm_row(pin, gw, lane);
    if (lane < 16)
        *(float2*)(pout + (size_t)gw * 32 + lane * 2) = r;
}

// seed: q0 = local * rs; also zero the sentinel row NN of both buffers
__global__ void k_seed(__half* __restrict__ qA, __half* __restrict__ qB) {
    int i = blockIdx.x * blockDim.x + threadIdx.x;
    if (i >= (NN + 1) * 16) return;
    int row = i >> 4, fp = i & 15;
    if (row == NN) {
        *(__half2*)(qA + (size_t)NN * 32 + fp * 2) = __floats2half2_rn(0.f, 0.f);
        *(__half2*)(qB + (size_t)NN * 32 + fp * 2) = __floats2half2_rn(0.f, 0.f);
        return;
    }
    float rs = g_rs[row];
    float2 lf = __half22float2(*(const __half2*)(g_local_h + (size_t)row * 32 + fp * 2));
    *(__half2*)(qB + (size_t)row * 32 + fp * 2) = __floats2half2_rn(lf.x * rs, lf.y * rs);
}

// ---------------- launch ----------------
extern "C" void kernel_launch(void* const* d_in, const int* in_sizes, int n_in,
                              void* d_out, int out_size) {
    const float* x    = (const float*)d_in[0];
    const float* w1   = (const float*)d_in[1];
    const float* w2   = (const float*)d_in[2];
    const int*   rows = (const int*)d_in[3];
    const int*   cols = (const int*)d_in[4];
    float*       out  = (float*)d_out;

    int E = in_sizes[3];
    if (E > EE) E = EE;

    // CSR build
    k_zero_cnt<<<(NN + 255) / 256, 256>>>();
    k_hist<<<(E + 255) / 256, 256>>>(rows, E);
    int nb = (NN + 2047) / 2048;
    k_scanA<<<nb, 1024>>>();
    k_scanB<<<1, 32>>>(nb);
    k_scanC<<<nb, 1024>>>(E);
    k_scatter<<<(E + 255) / 256, 256>>>(rows, cols, E);

    // MLP (tensor cores)
    cudaFuncSetAttribute(k_mlp_mma, cudaFuncAttributeMaxDynamicSharedMemorySize, MLP_SMEM_BYTES);
    k_mlp_mma<<<(NN + 127) / 128, 256, MLP_SMEM_BYTES>>>(x, w1, w2);

    __half *pA, *pB;
    cudaGetSymbolAddress((void**)&pA, g_pA);
    cudaGetSymbolAddress((void**)&pB, g_pB);
    k_seed<<<((NN + 1) * 16 + 255) / 256, 256>>>(pA, pB);

    const __half* pin = pB;
    int grid = (NN * 32 + 255) / 256;
    for (int i = 0; i < NITER; i++) {
        if (i == NITER - 1) {
            k_spmm_f<<<grid, 256>>>(pin, out);
        } else {
            __half* po = (i & 1) ? pB : pA;
            k_spmm_h<<<grid, 256>>>(pin, po);
            pin = po;
        }
    }
}